// round 13
// baseline (speedup 1.0000x reference)
#include <cuda_runtime.h>
#include <cstdint>

// HashGrid encode: 16 levels, F=2, T=2^19, base_res=16, per_level_scale=2.0,
// smoothstep, 2D. Levels 0..5 dense, 6..15 hashed.
//
// v13 = v12 (78.6us: fused two 8-level halves, one launch, interleaved by
// blockIdx parity) with finer scheduling granularity:
//   block 256 -> 128, __launch_bounds__(128, 13) (39-reg budget, a 1-reg
//   squeeze) -> warp cap 48 -> 52/SM and 4x finer CTA allocation, targeting
//   the ~18% L1-idle (warp starvation) that is the only remaining headroom.
// Body unchanged: pair-merged gathers (conditional swap on hashed levels),
// 16x16 half-warp butterfly transpose, 64B coalesced half-row stores.

#define NLEVELS 16
#define LOG2_T 19
#define TSIZE (1u << LOG2_T)
#define PRIME1 2654435761u

template <int L_BEGIN>
__device__ __forceinline__ void half_body(
    int i, int lane, float x0, float x1,
    const float2* __restrict__ table,
    float* __restrict__ out, int n)
{
    float acc[16];

#pragma unroll
    for (int k = 0; k < 8; ++k) {
        const int l = L_BEGIN + k;
        const unsigned res = 16u << l;                 // power of two
        const float scale = (float)(res - 1u);

        float p0 = x0 * scale + 0.5f;
        float p1 = x1 * scale + 0.5f;
        float fl0 = floorf(p0);
        float fl1 = floorf(p1);
        float fr0 = p0 - fl0;
        float fr1 = p1 - fl1;
        unsigned g0 = (unsigned)(int)fl0;
        unsigned g1 = (unsigned)(int)fl1;

        // smoothstep weights
        float w0 = fr0 * fr0 * (3.0f - 2.0f * fr0);
        float w1 = fr1 * fr1 * (3.0f - 2.0f * fr1);

        unsigned i00, i10, i01, i11;
        if (l <= 5) {
            const unsigned mask = (res * res) - 1u;
            unsigned b0 = g0 + g1 * res;
            unsigned b1 = b0 + res;
            i00 = b0 & mask;        i10 = (b0 + 1u) & mask;
            i01 = b1 & mask;        i11 = (b1 + 1u) & mask;
        } else {
            const unsigned hmask = TSIZE - 1u;
            unsigned hy0 = g1 * PRIME1;
            unsigned hy1 = hy0 + PRIME1;
            i00 = (g0 ^ hy0) & hmask;        i10 = ((g0 + 1u) ^ hy0) & hmask;
            i01 = (g0 ^ hy1) & hmask;        i11 = ((g0 + 1u) ^ hy1) & hmask;
        }

        const float2* tl = table + (size_t)l * TSIZE;
        float2 f00, f10, f01, f11;

        if ((g0 & 1u) == 0u) {
            // x even: row corners are adjacent 8B entries -> one aligned float4.
            // Dense levels: i00/i01 provably even. Hashed: may be odd -> swap.
            const float4* tl4 = reinterpret_cast<const float4*>(tl);
            float4 v0 = __ldg(tl4 + (i00 >> 1));
            float4 v1 = __ldg(tl4 + (i01 >> 1));
            if (l <= 5) {
                f00 = make_float2(v0.x, v0.y); f10 = make_float2(v0.z, v0.w);
                f01 = make_float2(v1.x, v1.y); f11 = make_float2(v1.z, v1.w);
            } else {
                if (i00 & 1u) { f00 = make_float2(v0.z, v0.w); f10 = make_float2(v0.x, v0.y); }
                else          { f00 = make_float2(v0.x, v0.y); f10 = make_float2(v0.z, v0.w); }
                if (i01 & 1u) { f01 = make_float2(v1.z, v1.w); f11 = make_float2(v1.x, v1.y); }
                else          { f01 = make_float2(v1.x, v1.y); f11 = make_float2(v1.z, v1.w); }
            }
        } else {
            f00 = __ldg(tl + i00);
            f10 = __ldg(tl + i10);
            f01 = __ldg(tl + i01);
            f11 = __ldg(tl + i11);
        }

        float c00 = (1.0f - w0) * (1.0f - w1);
        float c10 = w0 * (1.0f - w1);
        float c01 = (1.0f - w0) * w1;
        float c11 = w0 * w1;

        acc[2 * k]     = c00 * f00.x + c10 * f10.x + c01 * f01.x + c11 * f11.x;
        acc[2 * k + 1] = c00 * f00.y + c10 * f10.y + c01 * f01.y + c11 * f11.y;
    }

    const int wbase = i & ~31;   // first point of this warp
    if (wbase + 32 <= n) {
        // 16x16 butterfly transpose within each half-warp.
#pragma unroll
        for (int step = 1; step < 16; step <<= 1) {
            const bool up = (lane & step) != 0;
#pragma unroll
            for (int t = 0; t < 16; ++t) {
                if ((t & step) == 0) {
                    float lo = acc[t], hi = acc[t + step];
                    float send = up ? lo : hi;
                    float recv = __shfl_xor_sync(0xffffffffu, send, step);
                    if (up) acc[t] = recv; else acc[t + step] = recv;
                }
            }
        }
        // lanes 0..15 -> point (wbase+j) channels [2*L_BEGIN..+16),
        // lanes 16..31 -> point (wbase+16+j). 64B contiguous per half-warp.
        const int c0 = 2 * L_BEGIN;
        float* ob = out + (size_t)(wbase + (lane >> 4) * 16) * 32 + c0 + (lane & 15);
#pragma unroll
        for (int j = 0; j < 16; ++j)
            ob[j * 32] = acc[j];
    } else {
        // tail warp (not hit for N = 524288)
        float* ot = out + (size_t)i * 32 + 2 * L_BEGIN;
#pragma unroll
        for (int c = 0; c < 16; ++c) ot[c] = acc[c];
    }
}

__global__ __launch_bounds__(128, 13) void hashgrid_fused_kernel(
    const float2* __restrict__ x,          // [N] points in [-1,1]
    const float2* __restrict__ table,      // [16 * T] float2 entries
    float* __restrict__ out,               // [N, 32]
    int n)
{
    const int lane = threadIdx.x & 31;
    const int half = blockIdx.x & 1;       // 0: levels 0..7, 1: levels 8..15
    const int blk  = blockIdx.x >> 1;
    const int i = blk * blockDim.x + threadIdx.x;
    if (i >= n) return;

    float2 xi = __ldg(&x[i]);
    float x0 = xi.x * 0.5f + 0.5f;
    float x1 = xi.y * 0.5f + 0.5f;

    if (half == 0)
        half_body<0>(i, lane, x0, x1, table, out, n);
    else
        half_body<8>(i, lane, x0, x1, table, out, n);
}

extern "C" void kernel_launch(void* const* d_in, const int* in_sizes, int n_in,
                              void* d_out, int out_size)
{
    const float2* x     = (const float2*)d_in[0];   // [N,2] float32
    const float2* table = (const float2*)d_in[1];   // [16, T, 2] float32
    float* out          = (float*)d_out;            // [N, 32] float32

    int n = in_sizes[0] / 2;
    int threads = 128;
    int blocks = (n + threads - 1) / threads;
    hashgrid_fused_kernel<<<2 * blocks, threads>>>(x, table, out, n);
}

// round 14
// speedup vs baseline: 1.0433x; 1.0433x over previous
#include <cuda_runtime.h>
#include <cstdint>

// HashGrid encode: 16 levels, F=2, T=2^19, base_res=16, per_level_scale=2.0,
// smoothstep, 2D. Levels 0..5 dense, 6..15 hashed.
//
// v14 = v12 (78.6us best: fused 8-level halves, pair-merged gathers,
// half-warp transpose stores) with two scheduling-shape changes only:
//  (a) block 256 -> 128, NO launch_bounds (v13 lesson: the 39-reg pin made
//      ptxas squeeze to 32 regs and de-batch loads; leave codegen at ~40).
//  (b) long-work-first: hashed-half CTAs (~2x runtime of dense-half) occupy
//      low blockIdx so they start in wave 1; short dense CTAs pack the tail.

#define NLEVELS 16
#define LOG2_T 19
#define TSIZE (1u << LOG2_T)
#define PRIME1 2654435761u

template <int L_BEGIN>
__device__ __forceinline__ void half_body(
    int i, int lane, float x0, float x1,
    const float2* __restrict__ table,
    float* __restrict__ out, int n)
{
    float acc[16];

#pragma unroll
    for (int k = 0; k < 8; ++k) {
        const int l = L_BEGIN + k;
        const unsigned res = 16u << l;                 // power of two
        const float scale = (float)(res - 1u);

        float p0 = x0 * scale + 0.5f;
        float p1 = x1 * scale + 0.5f;
        float fl0 = floorf(p0);
        float fl1 = floorf(p1);
        float fr0 = p0 - fl0;
        float fr1 = p1 - fl1;
        unsigned g0 = (unsigned)(int)fl0;
        unsigned g1 = (unsigned)(int)fl1;

        // smoothstep weights
        float w0 = fr0 * fr0 * (3.0f - 2.0f * fr0);
        float w1 = fr1 * fr1 * (3.0f - 2.0f * fr1);

        unsigned i00, i10, i01, i11;
        if (l <= 5) {
            const unsigned mask = (res * res) - 1u;
            unsigned b0 = g0 + g1 * res;
            unsigned b1 = b0 + res;
            i00 = b0 & mask;        i10 = (b0 + 1u) & mask;
            i01 = b1 & mask;        i11 = (b1 + 1u) & mask;
        } else {
            const unsigned hmask = TSIZE - 1u;
            unsigned hy0 = g1 * PRIME1;
            unsigned hy1 = hy0 + PRIME1;
            i00 = (g0 ^ hy0) & hmask;        i10 = ((g0 + 1u) ^ hy0) & hmask;
            i01 = (g0 ^ hy1) & hmask;        i11 = ((g0 + 1u) ^ hy1) & hmask;
        }

        const float2* tl = table + (size_t)l * TSIZE;
        float2 f00, f10, f01, f11;

        if ((g0 & 1u) == 0u) {
            // x even: row corners are adjacent 8B entries -> one aligned float4.
            // Dense levels: i00/i01 provably even. Hashed: may be odd -> swap.
            const float4* tl4 = reinterpret_cast<const float4*>(tl);
            float4 v0 = __ldg(tl4 + (i00 >> 1));
            float4 v1 = __ldg(tl4 + (i01 >> 1));
            if (l <= 5) {
                f00 = make_float2(v0.x, v0.y); f10 = make_float2(v0.z, v0.w);
                f01 = make_float2(v1.x, v1.y); f11 = make_float2(v1.z, v1.w);
            } else {
                if (i00 & 1u) { f00 = make_float2(v0.z, v0.w); f10 = make_float2(v0.x, v0.y); }
                else          { f00 = make_float2(v0.x, v0.y); f10 = make_float2(v0.z, v0.w); }
                if (i01 & 1u) { f01 = make_float2(v1.z, v1.w); f11 = make_float2(v1.x, v1.y); }
                else          { f01 = make_float2(v1.x, v1.y); f11 = make_float2(v1.z, v1.w); }
            }
        } else {
            f00 = __ldg(tl + i00);
            f10 = __ldg(tl + i10);
            f01 = __ldg(tl + i01);
            f11 = __ldg(tl + i11);
        }

        float c00 = (1.0f - w0) * (1.0f - w1);
        float c10 = w0 * (1.0f - w1);
        float c01 = (1.0f - w0) * w1;
        float c11 = w0 * w1;

        acc[2 * k]     = c00 * f00.x + c10 * f10.x + c01 * f01.x + c11 * f11.x;
        acc[2 * k + 1] = c00 * f00.y + c10 * f10.y + c01 * f01.y + c11 * f11.y;
    }

    const int wbase = i & ~31;   // first point of this warp
    if (wbase + 32 <= n) {
        // 16x16 butterfly transpose within each half-warp.
#pragma unroll
        for (int step = 1; step < 16; step <<= 1) {
            const bool up = (lane & step) != 0;
#pragma unroll
            for (int t = 0; t < 16; ++t) {
                if ((t & step) == 0) {
                    float lo = acc[t], hi = acc[t + step];
                    float send = up ? lo : hi;
                    float recv = __shfl_xor_sync(0xffffffffu, send, step);
                    if (up) acc[t] = recv; else acc[t + step] = recv;
                }
            }
        }
        // lanes 0..15 -> point (wbase+j) channels [2*L_BEGIN..+16),
        // lanes 16..31 -> point (wbase+16+j). 64B contiguous per half-warp.
        const int c0 = 2 * L_BEGIN;
        float* ob = out + (size_t)(wbase + (lane >> 4) * 16) * 32 + c0 + (lane & 15);
#pragma unroll
        for (int j = 0; j < 16; ++j)
            ob[j * 32] = acc[j];
    } else {
        // tail warp (not hit for N = 524288)
        float* ot = out + (size_t)i * 32 + 2 * L_BEGIN;
#pragma unroll
        for (int c = 0; c < 16; ++c) ot[c] = acc[c];
    }
}

__global__ void hashgrid_fused_kernel(
    const float2* __restrict__ x,          // [N] points in [-1,1]
    const float2* __restrict__ table,      // [16 * T] float2 entries
    float* __restrict__ out,               // [N, 32]
    int n,
    int blocks_per_half)
{
    const int lane = threadIdx.x & 31;
    // Long-work-first: first half of the grid = hashed levels 8..15,
    // second half = dense-ish levels 0..7.
    const bool hashed_half = (blockIdx.x < blocks_per_half);
    const int blk = hashed_half ? blockIdx.x : (blockIdx.x - blocks_per_half);
    const int i = blk * blockDim.x + threadIdx.x;
    if (i >= n) return;

    float2 xi = __ldg(&x[i]);
    float x0 = xi.x * 0.5f + 0.5f;
    float x1 = xi.y * 0.5f + 0.5f;

    if (hashed_half)
        half_body<8>(i, lane, x0, x1, table, out, n);
    else
        half_body<0>(i, lane, x0, x1, table, out, n);
}

extern "C" void kernel_launch(void* const* d_in, const int* in_sizes, int n_in,
                              void* d_out, int out_size)
{
    const float2* x     = (const float2*)d_in[0];   // [N,2] float32
    const float2* table = (const float2*)d_in[1];   // [16, T, 2] float32
    float* out          = (float*)d_out;            // [N, 32] float32

    int n = in_sizes[0] / 2;
    int threads = 128;
    int blocks = (n + threads - 1) / threads;
    hashgrid_fused_kernel<<<2 * blocks, threads>>>(x, table, out, n, blocks);
}